// round 11
// baseline (speedup 1.0000x reference)
#include <cuda_runtime.h>
#include <cuda_bf16.h>
#include <cstdint>

// ===========================================================================
// SplineCouplingLayer — fused HMMA, TM=16, 2 CTAs/SM (round 11)
//  - 76.6 KB smem -> 2 resident CTAs, 32 warps/SM: head/tail bubbles overlap
//  - no prefetch (8-warp/SMSP TLP hides operand latency), 64-reg budget
//  - fast-math intrinsics in spline tail
// ===========================================================================

#define B_ROWS  131072
#define DIM     64
#define D_IN    32
#define TAILB   3.0f

#define TM      16
#define THREADS 512

// strides (elements)
#define XT_S   33
#define XA_S   40
#define H_S    520
#define ST_S   776

// smem byte offsets (16B aligned)
#define SM_XT    0            // 16*33*4  = 2112
#define SM_BIAS  2112         // 1792*4   = 7168
#define SM_XAH   9280         // 16*40*2  = 1280
#define SM_XAL   10560        // 1280
#define SM_H1H   11840        // 16*520*2 = 16640
#define SM_H1L   28480        // 16640
#define SM_H2H   45120        // 16640
#define SM_H2L   61760        // 16640 (ends 78400)
#define SM_STASH 9280         // 16*776*4 = 49664 (overlays XA/H1/H2H after sync)
#define SM_TOTAL 78400

typedef unsigned int u32;

// W fragments interleaved: per (kc, nf): 32 lanes x uint4 {b0h, b1h, b0l, b1l}
__device__ u32 g_F1[2 * 64 * 32 * 4];
__device__ u32 g_F2[32 * 64 * 32 * 4];
__device__ u32 g_F3[32 * 96 * 32 * 4];

__device__ __forceinline__ u32 smem_u32(const void* p) {
    u32 a;
    asm("{ .reg .u64 t; cvta.to.shared.u64 t, %1; cvt.u32.u64 %0, t; }"
        : "=r"(a) : "l"(p));
    return a;
}

#define LDSM_X4(r0, r1, r2, r3, a) \
    asm volatile("ldmatrix.sync.aligned.m8n8.x4.shared.b16 {%0,%1,%2,%3}, [%4];" \
                 : "=r"(r0), "=r"(r1), "=r"(r2), "=r"(r3) : "r"(a))

__device__ __forceinline__ void mma_bf16(float* c, const u32* a, u32 b0, u32 b1) {
    asm volatile(
        "mma.sync.aligned.m16n8k16.row.col.f32.bf16.bf16.f32 "
        "{%0,%1,%2,%3},{%4,%5,%6,%7},{%8,%9},{%0,%1,%2,%3};"
        : "+f"(c[0]), "+f"(c[1]), "+f"(c[2]), "+f"(c[3])
        : "r"(a[0]), "r"(a[1]), "r"(a[2]), "r"(a[3]), "r"(b0), "r"(b1));
}

__device__ __forceinline__ u32 pk2(__nv_bfloat16 a, __nv_bfloat16 b) {
    return (u32)__bfloat16_as_ushort(a) | ((u32)__bfloat16_as_ushort(b) << 16);
}
__device__ __forceinline__ void split2(float x, float y, u32 &hi, u32 &lo) {
    __nv_bfloat16 xh = __float2bfloat16_rn(x);
    __nv_bfloat16 yh = __float2bfloat16_rn(y);
    __nv_bfloat16 xl = __float2bfloat16_rn(x - __bfloat162float(xh));
    __nv_bfloat16 yl = __float2bfloat16_rn(y - __bfloat162float(yh));
    hi = pk2(xh, yh);
    lo = pk2(xl, yl);
}

// A hi/lo fragments, 1 m-tile (16 rows)
__device__ __forceinline__ void load_afrag(
    u32 smb, int aoff_h, int aoff_l, int AS, int lane, int cK,
    u32 ah[4], u32 al[4])
{
    int r  = (lane & 7) + ((lane >> 3) & 1) * 8;
    int cc = cK + (lane >> 4) * 8;
    u32 off = (u32)(r * AS + cc) * 2;
    LDSM_X4(ah[0], ah[1], ah[2], ah[3], smb + aoff_h + off);
    LDSM_X4(al[0], al[1], al[2], al[3], smb + aoff_l + off);
}

// ---------------------------------------------------------------------------
// Layers 1/2: NT n-tiles per warp, 1 m-tile, no prefetch (TLP-hidden).
// ---------------------------------------------------------------------------
template<int NT, int NCH, int NFN, bool RELU>
__device__ __forceinline__ void do_layer_lin(
    char* sm, u32 smb, int tid, const u32* __restrict__ F, int bias_off,
    int aoff_h, int aoff_l, int AS, int hoff_h, int hoff_l)
{
    const int wid = tid >> 5, lane = tid & 31;
    const int nf0 = wid * NT;
    const uint4* Fq = (const uint4*)F;
    const float* bias_sm = (const float*)(sm + SM_BIAS) + bias_off;

    float acc[NT][4];
#pragma unroll
    for (int nt = 0; nt < NT; ++nt)
#pragma unroll
        for (int q = 0; q < 4; ++q) acc[nt][q] = 0.f;

#pragma unroll
    for (int c = 0; c < NCH; ++c) {
        uint4 b[NT];
#pragma unroll
        for (int nt = 0; nt < NT; ++nt)
            b[nt] = Fq[(c * NFN + nf0 + nt) * 32 + lane];
        u32 ah[4], al[4];
        load_afrag(smb, aoff_h, aoff_l, AS, lane, c * 16, ah, al);

#pragma unroll
        for (int nt = 0; nt < NT; ++nt)
            mma_bf16(acc[nt], ah, b[nt].x, b[nt].y);
#pragma unroll
        for (int nt = 0; nt < NT; ++nt)
            mma_bf16(acc[nt], al, b[nt].x, b[nt].y);
#pragma unroll
        for (int nt = 0; nt < NT; ++nt)
            mma_bf16(acc[nt], ah, b[nt].z, b[nt].w);
    }

    const int g  = lane >> 2;
    const int t2 = (lane & 3) * 2;
#pragma unroll
    for (int nt = 0; nt < NT; ++nt) {
        int col = wid * (NT * 8) + nt * 8 + t2;
        float b0v = bias_sm[col], b1v = bias_sm[col + 1];
        float v0 = acc[nt][0] + b0v, v1 = acc[nt][1] + b1v;
        float v2 = acc[nt][2] + b0v, v3 = acc[nt][3] + b1v;
        if (RELU) {
            v0 = fmaxf(v0, 0.f); v1 = fmaxf(v1, 0.f);
            v2 = fmaxf(v2, 0.f); v3 = fmaxf(v3, 0.f);
        }
        u32 h01, l01, h23, l23;
        split2(v0, v1, h01, l01);
        split2(v2, v3, h23, l23);
        int rA = g, rB = g + 8;
        u32 oA = (u32)(rA * H_S + col) * 2;
        u32 oB = (u32)(rB * H_S + col) * 2;
        *(u32*)(sm + hoff_h + oA) = h01;
        *(u32*)(sm + hoff_l + oA) = l01;
        *(u32*)(sm + hoff_h + oB) = h23;
        *(u32*)(sm + hoff_l + oB) = l23;
    }
}

// ---------------------------------------------------------------------------
// Layer 3: merged halves (NT=3 each), 1 m-tile; epilogue after caller sync.
// ---------------------------------------------------------------------------
__device__ __forceinline__ void do_layer3_main(
    char* sm, u32 smb, int tid, const u32* __restrict__ F,
    int aoff_h, int aoff_l, int AS, float acc[2][3][4])
{
    const int wid = tid >> 5, lane = tid & 31;
    const int nf0 = wid * 3;
    const uint4* Fq = (const uint4*)F;

#pragma unroll
    for (int hh = 0; hh < 2; ++hh)
#pragma unroll
        for (int nt = 0; nt < 3; ++nt)
#pragma unroll
            for (int q = 0; q < 4; ++q) acc[hh][nt][q] = 0.f;

#pragma unroll
    for (int c = 0; c < 32; ++c) {
        u32 ah[4], al[4];
        load_afrag(smb, aoff_h, aoff_l, AS, lane, c * 16, ah, al);
#pragma unroll
        for (int hh = 0; hh < 2; ++hh) {
            uint4 b[3];
#pragma unroll
            for (int nt = 0; nt < 3; ++nt)
                b[nt] = Fq[(c * 96 + hh * 48 + nf0 + nt) * 32 + lane];
#pragma unroll
            for (int nt = 0; nt < 3; ++nt)
                mma_bf16(acc[hh][nt], ah, b[nt].x, b[nt].y);
#pragma unroll
            for (int nt = 0; nt < 3; ++nt)
                mma_bf16(acc[hh][nt], al, b[nt].x, b[nt].y);
#pragma unroll
            for (int nt = 0; nt < 3; ++nt)
                mma_bf16(acc[hh][nt], ah, b[nt].z, b[nt].w);
        }
    }
}

__device__ __forceinline__ void do_layer3_epi(
    char* sm, int tid, float acc[2][3][4])
{
    const int wid = tid >> 5, lane = tid & 31;
    const float* bias_sm = (const float*)(sm + SM_BIAS) + 1024;
    const int g  = lane >> 2;
    const int t2 = (lane & 3) * 2;
#pragma unroll
    for (int hh = 0; hh < 2; ++hh)
#pragma unroll
        for (int nt = 0; nt < 3; ++nt) {
            int scol = hh * 384 + wid * 24 + nt * 8 + t2;
            float b0v = bias_sm[scol], b1v = bias_sm[scol + 1];
            int rA = g, rB = g + 8;
            *(float2*)(sm + SM_STASH + ((u32)rA * ST_S + scol) * 4)
                = make_float2(acc[hh][nt][0] + b0v, acc[hh][nt][1] + b1v);
            *(float2*)(sm + SM_STASH + ((u32)rB * ST_S + scol) * 4)
                = make_float2(acc[hh][nt][2] + b0v, acc[hh][nt][3] + b1v);
        }
}

// ---------------------------------------------------------------------------
__device__ __forceinline__ float softplusf(float z) {
    return (z > 20.f) ? z : __logf(1.f + __expf(z));
}
__device__ __forceinline__ void spline_eval(const float raw[23], float xv,
                                            float &y_out, float &ld_out)
{
    float w[8], h[8];
    float mw = raw[0], mh = raw[8];
#pragma unroll
    for (int i = 1; i < 8; ++i) { mw = fmaxf(mw, raw[i]); mh = fmaxf(mh, raw[8 + i]); }
    float sw = 0.f, sh = 0.f;
#pragma unroll
    for (int i = 0; i < 8; ++i) {
        w[i] = __expf(raw[i] - mw); sw += w[i];
        h[i] = __expf(raw[8 + i] - mh); sh += h[i];
    }
    float iw = 6.f / sw, ih = 6.f / sh;
#pragma unroll
    for (int i = 0; i < 8; ++i) { w[i] *= iw; h[i] *= ih; }
    float der[9]; der[0] = 1.f; der[8] = 1.f;
#pragma unroll
    for (int i = 0; i < 7; ++i) der[i + 1] = softplusf(raw[16 + i]);
    float cw[9], ch[9]; cw[0] = -TAILB; ch[0] = -TAILB;
#pragma unroll
    for (int i = 0; i < 8; ++i) { cw[i + 1] = cw[i] + w[i]; ch[i + 1] = ch[i] + h[i]; }
    bool inside = (xv >= -TAILB) && (xv <= TAILB);
    float xc = fminf(fmaxf(xv, -TAILB + 1e-6f), TAILB - 1e-6f);
    int idx = 0;
#pragma unroll
    for (int i = 1; i <= 8; ++i) idx += (cw[i] < xc) ? 1 : 0;
    idx = min(idx, 7);
    float wk = w[0], hk = h[0], dk = der[0], dk1 = der[1], cwk = cw[0], chk = ch[0];
#pragma unroll
    for (int i = 1; i < 8; ++i) {
        bool sel = (idx == i);
        wk = sel ? w[i] : wk;   hk = sel ? h[i] : hk;
        dk = sel ? der[i] : dk; dk1 = sel ? der[i + 1] : dk1;
        cwk = sel ? cw[i] : cwk; chk = sel ? ch[i] : chk;
    }
    float xi = fminf(fmaxf((xc - cwk) / wk, 1e-6f), 1.f - 1e-6f);
    float om = 1.f - xi;
    float s = hk / wk;
    float num = hk * (s * xi * xi + dk * xi * om);
    float den = s + (dk + dk1 - 2.f * s) * xi * om;
    float yin = chk + num / den;
    float nld = s * s * (dk1 * xi * xi + 2.f * s * xi * om + dk * om * om);
    float ldin = __logf(nld + 1e-8f) - __logf(den * den + 1e-8f);
    y_out = inside ? yin : xv;
    ld_out = inside ? ldin : 0.f;
}

// ---------------------------------------------------------------------------
__global__ void __launch_bounds__(THREADS, 2)
spline_fused(const float* __restrict__ x,
             const float* __restrict__ b1, const float* __restrict__ b2,
             const float* __restrict__ b3, float* __restrict__ out)
{
    extern __shared__ char sm[];
    const u32 smb = smem_u32(sm);
    const int tid  = threadIdx.x;
    const int wid  = tid >> 5, lane = tid & 31;
    const int row0 = blockIdx.x * TM;

    // preload all biases (1792 floats)
    {
        float* bias_sm = (float*)(sm + SM_BIAS);
        for (int i = tid; i < 1792; i += THREADS) {
            float v;
            if (i < 512)       v = b1[i];
            else if (i < 1024) v = b2[i - 512];
            else { int j = i - 1024; v = (j < 736) ? b3[j] : 0.f; }
            bias_sm[i] = v;
        }
    }
    // x tile: masked -> XA hi/lo + passthrough; transform -> XT
#pragma unroll
    for (int it = 0; it < 2; ++it) {
        int idx = tid + it * THREADS;
        int r = idx >> 6, c = idx & 63;
        float v = x[(size_t)(row0 + r) * DIM + c];
        if (c < D_IN) {
            out[(size_t)(row0 + r) * DIM + c] = v;
            __nv_bfloat16 hh = __float2bfloat16_rn(v);
            __nv_bfloat16 ll = __float2bfloat16_rn(v - __bfloat162float(hh));
            *(__nv_bfloat16*)(sm + SM_XAH + (u32)(r * XA_S + c) * 2) = hh;
            *(__nv_bfloat16*)(sm + SM_XAL + (u32)(r * XA_S + c) * 2) = ll;
        } else {
            *(float*)(sm + SM_XT + (u32)(r * XT_S + (c - D_IN)) * 4) = v;
        }
    }
    __syncthreads();

    do_layer_lin<4, 2, 64, true>(sm, smb, tid, g_F1, 0,
                                 SM_XAH, SM_XAL, XA_S, SM_H1H, SM_H1L);
    __syncthreads();
    do_layer_lin<4, 32, 64, true>(sm, smb, tid, g_F2, 512,
                                  SM_H1H, SM_H1L, H_S, SM_H2H, SM_H2L);
    __syncthreads();

    float acc3[2][3][4];
    do_layer3_main(sm, smb, tid, g_F3, SM_H2H, SM_H2L, H_S, acc3);
    __syncthreads();                 // all warps done reading H2 -> stash may overlay
    do_layer3_epi(sm, tid, acc3);
    __syncthreads();

    // spline: warp w -> row w, lane -> dim
    {
        const float* stashf = (const float*)(sm + SM_STASH);
        const float* xtf    = (const float*)(sm + SM_XT);
        int row = wid, d = lane;
        float raw[23];
        const float* rp = stashf + (u32)row * ST_S + d * 23;
#pragma unroll
        for (int j = 0; j < 23; ++j) raw[j] = rp[j];
        float xv = xtf[row * XT_S + d];
        float yv, ld;
        spline_eval(raw, xv, yv, ld);
        int gr = row0 + row;
        out[(size_t)gr * DIM + D_IN + d] = yv;
#pragma unroll
        for (int off = 16; off; off >>= 1)
            ld += __shfl_xor_sync(0xffffffffu, ld, off);
        if (d == 0) out[(size_t)B_ROWS * DIM + gr] = ld;
    }
}

// ---------------------------------------------------------------------------
// prep: pack W into interleaved fragment-order uint4 {b0h, b1h, b0l, b1l}
// ---------------------------------------------------------------------------
__device__ __forceinline__ void frag_pack(
    const float* __restrict__ W, int N, int nvalid, int k0, int n, int t,
    u32* __restrict__ F, u32 base)
{
    float w00 = 0.f, w01 = 0.f, w10 = 0.f, w11 = 0.f;
    if (n < nvalid) {
        w00 = W[(size_t)(k0 + 2 * t)     * N + n];
        w01 = W[(size_t)(k0 + 2 * t + 1) * N + n];
        w10 = W[(size_t)(k0 + 2 * t + 8) * N + n];
        w11 = W[(size_t)(k0 + 2 * t + 9) * N + n];
    }
    u32 b0h, b0l, b1h, b1l;
    split2(w00, w01, b0h, b0l);
    split2(w10, w11, b1h, b1l);
    ((uint4*)F)[base] = make_uint4(b0h, b1h, b0l, b1l);
}

__global__ void __launch_bounds__(256)
prep_kernel(const float* __restrict__ W1, const float* __restrict__ W2,
            const float* __restrict__ W3)
{
    const int T1 = 2 * 64 * 32;
    const int T2 = 32 * 64 * 32;
    const int T3 = 32 * 96 * 32;
    const int TOT = T1 + T2 + T3;
    for (int id = blockIdx.x * 256 + threadIdx.x; id < TOT;
         id += gridDim.x * 256) {
        if (id < T1) {
            int lane = id & 31, fid = id >> 5;
            int nf = fid % 64, kc = fid / 64;
            frag_pack(W1, 512, 512, kc * 16, nf * 8 + (lane >> 2), lane & 3,
                      g_F1, (u32)(fid * 32 + lane));
        } else if (id < T1 + T2) {
            int i = id - T1;
            int lane = i & 31, fid = i >> 5;
            int nf = fid % 64, kc = fid / 64;
            frag_pack(W2, 512, 512, kc * 16, nf * 8 + (lane >> 2), lane & 3,
                      g_F2, (u32)(fid * 32 + lane));
        } else {
            int i = id - T1 - T2;
            int lane = i & 31, fid = i >> 5;
            int nf = fid % 96, kc = fid / 96;
            frag_pack(W3, 736, 736, kc * 16, nf * 8 + (lane >> 2), lane & 3,
                      g_F3, (u32)(fid * 32 + lane));
        }
    }
}

// ---------------------------------------------------------------------------
extern "C" void kernel_launch(void* const* d_in, const int* in_sizes, int n_in,
                              void* d_out, int out_size)
{
    (void)in_sizes; (void)n_in; (void)out_size;
    const float* x  = (const float*)d_in[0];
    const float* W1 = (const float*)d_in[1];
    const float* b1 = (const float*)d_in[2];
    const float* W2 = (const float*)d_in[3];
    const float* b2 = (const float*)d_in[4];
    const float* W3 = (const float*)d_in[5];
    const float* b3 = (const float*)d_in[6];
    float* out = (float*)d_out;

    prep_kernel<<<656, 256>>>(W1, W2, W3);

    cudaFuncSetAttribute(spline_fused,
                         cudaFuncAttributeMaxDynamicSharedMemorySize, SM_TOTAL);
    spline_fused<<<B_ROWS / TM, THREADS, SM_TOTAL>>>(x, b1, b2, b3, out);
}